// round 1
// baseline (speedup 1.0000x reference)
#include <cuda_runtime.h>
#include <math.h>
#include <float.h>

#define Bb 16
#define Ss 128
#define Tt 128
#define Hh 1024
#define Vv 32000
#define BOSTOK 1

// ---------------- scratch (device globals; no allocs allowed) ----------------
__device__ float g_kproj[Bb * Ss * Hh];          // 8 MB
__device__ float g_H[(Tt + 1) * Bb * Hh];        // hidden states, 8.45 MB
__device__ float g_q[Bb * Hh];
__device__ float g_scores[Bb * Ss];
__device__ float g_ctx[Bb * Hh];

// ---------------- math helpers ----------------
__device__ __forceinline__ float fast_tanh(float x) {
    float xc = fminf(fmaxf(x, -15.f), 15.f);
    float t = __expf(2.f * xc);
    return __fdividef(t - 1.f, t + 1.f);
}
__device__ __forceinline__ float fast_sigmoid(float x) {
    return __fdividef(1.f, 1.f + __expf(-x));
}

// ---------------- generic fp32 GEMM: C[m,n] = sum_k A[m,k]*B[n,k] (+bias) ----
// A==nullptr  -> A = g_H + Bb*Hh   (hidden states rows (t,b), skipping h0)
// dst==nullptr-> C = g_kproj
// remap!=0    -> output row m=(t*Bb+b) is written at dst + (b*Tt+t)*N
__global__ __launch_bounds__(256) void gemm_tn_kernel(
    const float* __restrict__ A, const float* __restrict__ Bw,
    const float* __restrict__ bias, float* __restrict__ dst,
    int M, int N, int K, int remap)
{
    __shared__ float sA[16][64];
    __shared__ float sB[16][64];
    const int tid = threadIdx.x;
    const int bm = blockIdx.y * 64;
    const int bn = blockIdx.x * 64;
    const int lrow = tid >> 2;          // 0..63
    const int lk = (tid & 3) << 2;      // 0,4,8,12
    const int tx = tid & 15;
    const int ty = tid >> 4;

    const float* Abase = A ? A : (g_H + (size_t)Bb * Hh);
    const float* Ap = Abase + (size_t)(bm + lrow) * K + lk;
    const float* Bp = Bw + (size_t)(bn + lrow) * K + lk;

    float acc[4][4] = {};

    for (int k0 = 0; k0 < K; k0 += 16) {
        float4 av = *(const float4*)(Ap + k0);
        float4 bv = *(const float4*)(Bp + k0);
        sA[lk + 0][lrow] = av.x; sA[lk + 1][lrow] = av.y;
        sA[lk + 2][lrow] = av.z; sA[lk + 3][lrow] = av.w;
        sB[lk + 0][lrow] = bv.x; sB[lk + 1][lrow] = bv.y;
        sB[lk + 2][lrow] = bv.z; sB[lk + 3][lrow] = bv.w;
        __syncthreads();
#pragma unroll
        for (int kk = 0; kk < 16; kk++) {
            float4 a = *(const float4*)&sA[kk][ty << 2];
            float4 b = *(const float4*)&sB[kk][tx << 2];
            acc[0][0] = fmaf(a.x, b.x, acc[0][0]); acc[0][1] = fmaf(a.x, b.y, acc[0][1]);
            acc[0][2] = fmaf(a.x, b.z, acc[0][2]); acc[0][3] = fmaf(a.x, b.w, acc[0][3]);
            acc[1][0] = fmaf(a.y, b.x, acc[1][0]); acc[1][1] = fmaf(a.y, b.y, acc[1][1]);
            acc[1][2] = fmaf(a.y, b.z, acc[1][2]); acc[1][3] = fmaf(a.y, b.w, acc[1][3]);
            acc[2][0] = fmaf(a.z, b.x, acc[2][0]); acc[2][1] = fmaf(a.z, b.y, acc[2][1]);
            acc[2][2] = fmaf(a.z, b.z, acc[2][2]); acc[2][3] = fmaf(a.z, b.w, acc[2][3]);
            acc[3][0] = fmaf(a.w, b.x, acc[3][0]); acc[3][1] = fmaf(a.w, b.y, acc[3][1]);
            acc[3][2] = fmaf(a.w, b.z, acc[3][2]); acc[3][3] = fmaf(a.w, b.w, acc[3][3]);
        }
        __syncthreads();
    }

#pragma unroll
    for (int i = 0; i < 4; i++) {
        int m = bm + (ty << 2) + i;
        float* crow;
        if (remap) {
            int tt = m >> 4, bbi = m & 15;
            crow = dst + ((size_t)bbi * Tt + tt) * N;
        } else if (dst) {
            crow = dst + (size_t)m * N;
        } else {
            crow = g_kproj + (size_t)m * N;
        }
        int n = bn + (tx << 2);
        float4 o = make_float4(acc[i][0], acc[i][1], acc[i][2], acc[i][3]);
        if (bias) { o.x += bias[n]; o.y += bias[n + 1]; o.z += bias[n + 2]; o.w += bias[n + 3]; }
        *(float4*)(crow + n) = o;
    }
}

// ---------------- h0 init / hT copy ----------------
__global__ void init_h_kernel(const float* __restrict__ h0) {
    int i = blockIdx.x * 256 + threadIdx.x;
    if (i < Bb * Hh) g_H[i] = h0[i];
}
__global__ void copy_hT_kernel(float* __restrict__ dst) {
    int i = blockIdx.x * 256 + threadIdx.x;
    if (i < Bb * Hh) dst[i] = g_H[(size_t)Tt * Bb * Hh + i];
}

// ---------------- per-step: q = h @ Wq^T ----------------
// grid 64 blocks x 256 threads; thread (m = tid%16, n = blk*16 + tid/16)
__global__ __launch_bounds__(256) void q_kernel(const float* __restrict__ Wq, int t)
{
    const float* h = g_H + (size_t)t * Bb * Hh;
    int m = threadIdx.x & 15;
    int n = blockIdx.x * 16 + (threadIdx.x >> 4);
    const float4* a = (const float4*)(h + (size_t)m * Hh);
    const float4* w = (const float4*)(Wq + (size_t)n * Hh);
    float acc = 0.f;
#pragma unroll 8
    for (int k = 0; k < Hh / 4; k++) {
        float4 av = a[k], wv = w[k];
        acc = fmaf(av.x, wv.x, acc); acc = fmaf(av.y, wv.y, acc);
        acc = fmaf(av.z, wv.z, acc); acc = fmaf(av.w, wv.w, acc);
    }
    g_q[m * Hh + n] = acc;
}

// ---------------- per-step: scores[b,s] = v . tanh(q[b]+kproj[b,s]) ----------
__global__ __launch_bounds__(128) void scores_kernel(const float* __restrict__ v_att)
{
    int bs = blockIdx.x;
    int b = bs >> 7;
    const float* qr = g_q + (size_t)b * Hh;
    const float* kp = g_kproj + (size_t)bs * Hh;
    float acc = 0.f;
    for (int h = threadIdx.x; h < Hh; h += 128)
        acc = fmaf(v_att[h], fast_tanh(qr[h] + kp[h]), acc);
#pragma unroll
    for (int o = 16; o; o >>= 1) acc += __shfl_xor_sync(~0u, acc, o);
    __shared__ float sr[4];
    if ((threadIdx.x & 31) == 0) sr[threadIdx.x >> 5] = acc;
    __syncthreads();
    if (threadIdx.x == 0) g_scores[bs] = sr[0] + sr[1] + sr[2] + sr[3];
}

// ------- per-step: softmax over S (redundant per h-chunk) + ctx; store attw --
// grid (Bb, 8) x 128 threads
__global__ __launch_bounds__(128) void ctx_kernel(const float* __restrict__ enc,
                                                  float* __restrict__ attw, int t)
{
    int b = blockIdx.x, hc = blockIdx.y, tid = threadIdx.x;
    __shared__ float w[Ss];
    __shared__ float sred[4];

    float sc = g_scores[b * Ss + tid];
    float mx = sc;
#pragma unroll
    for (int o = 16; o; o >>= 1) mx = fmaxf(mx, __shfl_xor_sync(~0u, mx, o));
    if ((tid & 31) == 0) sred[tid >> 5] = mx;
    __syncthreads();
    mx = fmaxf(fmaxf(sred[0], sred[1]), fmaxf(sred[2], sred[3]));
    float e = __expf(sc - mx);
    float sm = e;
#pragma unroll
    for (int o = 16; o; o >>= 1) sm += __shfl_xor_sync(~0u, sm, o);
    __syncthreads();  // protect sred before reuse
    if ((tid & 31) == 0) sred[tid >> 5] = sm;
    __syncthreads();
    sm = sred[0] + sred[1] + sred[2] + sred[3];
    float wv = __fdividef(e, sm);
    w[tid] = wv;
    if (hc == 0) attw[((size_t)b * Tt + t) * Ss + tid] = wv;
    __syncthreads();

    int h = hc * 128 + tid;
    const float* ep = enc + ((size_t)b * Ss) * Hh + h;
    float acc = 0.f;
#pragma unroll 8
    for (int s = 0; s < Ss; s++) acc = fmaf(w[s], ep[(size_t)s * Hh], acc);
    g_ctx[b * Hh + h] = acc;
}

// ---------------- per-step: fused GRU gates + state update ----------------
// grid 256 blocks x 256 threads. Block handles 4 j's, 16 batch rows, K split 4-way.
__global__ __launch_bounds__(256) void gru_kernel(
    const float* __restrict__ emb, const int* __restrict__ tgt,
    const float* __restrict__ Wih, const float* __restrict__ Whh,
    const float* __restrict__ bih, const float* __restrict__ bhh, int t)
{
    const float* hprev = g_H + (size_t)t * Bb * Hh;
    float* hnew = g_H + (size_t)(t + 1) * Bb * Hh;
    int tid = threadIdx.x;
    int m = tid & 15;
    int jl = (tid >> 4) & 3;
    int kq = tid >> 6;                  // 0..3 K-split
    int j = blockIdx.x * 4 + jl;

    int xi = (t == 0) ? BOSTOK : tgt[m * Tt + (t - 1)];
    // x = [emb[xi], ctx[m]] of length 2H; kq 0,1 cover emb half, kq 2,3 ctx half
    const float* xsrc = (kq < 2) ? (emb + (size_t)xi * Hh + kq * 512)
                                 : (g_ctx + (size_t)m * Hh + (kq - 2) * 512);

    const float4* xs = (const float4*)xsrc;
    const float4* w0 = (const float4*)(Wih + (size_t)(0 * Hh + j) * (2 * Hh) + kq * 512);
    const float4* w1 = (const float4*)(Wih + (size_t)(1 * Hh + j) * (2 * Hh) + kq * 512);
    const float4* w2 = (const float4*)(Wih + (size_t)(2 * Hh + j) * (2 * Hh) + kq * 512);
    float a0 = 0.f, a1 = 0.f, a2 = 0.f;
#pragma unroll 4
    for (int i = 0; i < 128; i++) {
        float4 x = xs[i];
        float4 u = w0[i];
        a0 = fmaf(x.x, u.x, a0); a0 = fmaf(x.y, u.y, a0); a0 = fmaf(x.z, u.z, a0); a0 = fmaf(x.w, u.w, a0);
        float4 v = w1[i];
        a1 = fmaf(x.x, v.x, a1); a1 = fmaf(x.y, v.y, a1); a1 = fmaf(x.z, v.z, a1); a1 = fmaf(x.w, v.w, a1);
        float4 q = w2[i];
        a2 = fmaf(x.x, q.x, a2); a2 = fmaf(x.y, q.y, a2); a2 = fmaf(x.z, q.z, a2); a2 = fmaf(x.w, q.w, a2);
    }

    const float4* hs = (const float4*)(hprev + (size_t)m * Hh + kq * 256);
    const float4* v0 = (const float4*)(Whh + (size_t)(0 * Hh + j) * Hh + kq * 256);
    const float4* v1 = (const float4*)(Whh + (size_t)(1 * Hh + j) * Hh + kq * 256);
    const float4* v2 = (const float4*)(Whh + (size_t)(2 * Hh + j) * Hh + kq * 256);
    float b0 = 0.f, b1 = 0.f, b2 = 0.f;
#pragma unroll 4
    for (int i = 0; i < 64; i++) {
        float4 x = hs[i];
        float4 u = v0[i];
        b0 = fmaf(x.x, u.x, b0); b0 = fmaf(x.y, u.y, b0); b0 = fmaf(x.z, u.z, b0); b0 = fmaf(x.w, u.w, b0);
        float4 v = v1[i];
        b1 = fmaf(x.x, v.x, b1); b1 = fmaf(x.y, v.y, b1); b1 = fmaf(x.z, v.z, b1); b1 = fmaf(x.w, v.w, b1);
        float4 q = v2[i];
        b2 = fmaf(x.x, q.x, b2); b2 = fmaf(x.y, q.y, b2); b2 = fmaf(x.z, q.z, b2); b2 = fmaf(x.w, q.w, b2);
    }

    __shared__ float red[4][64][6];
    int sl = jl * 16 + m;
    red[kq][sl][0] = a0; red[kq][sl][1] = a1; red[kq][sl][2] = a2;
    red[kq][sl][3] = b0; red[kq][sl][4] = b1; red[kq][sl][5] = b2;
    __syncthreads();
    if (kq == 0) {
        float gx0 = red[0][sl][0] + red[1][sl][0] + red[2][sl][0] + red[3][sl][0] + bih[j];
        float gx1 = red[0][sl][1] + red[1][sl][1] + red[2][sl][1] + red[3][sl][1] + bih[Hh + j];
        float gx2 = red[0][sl][2] + red[1][sl][2] + red[2][sl][2] + red[3][sl][2] + bih[2 * Hh + j];
        float gh0 = red[0][sl][3] + red[1][sl][3] + red[2][sl][3] + red[3][sl][3] + bhh[j];
        float gh1 = red[0][sl][4] + red[1][sl][4] + red[2][sl][4] + red[3][sl][4] + bhh[Hh + j];
        float gh2 = red[0][sl][5] + red[1][sl][5] + red[2][sl][5] + red[3][sl][5] + bhh[2 * Hh + j];
        float r = fast_sigmoid(gx0 + gh0);
        float z = fast_sigmoid(gx1 + gh1);
        float n = fast_tanh(gx2 + r * gh2);
        float hp = hprev[m * Hh + j];
        hnew[m * Hh + j] = (1.f - z) * n + z * hp;
    }
}

// ---------------- final: in-place log_softmax over V per (b,t) row -----------
__global__ __launch_bounds__(256) void logsoftmax_kernel(float* __restrict__ out)
{
    float* row = out + (size_t)blockIdx.x * Vv;
    int tid = threadIdx.x;
    __shared__ float sred[8];

    float mx = -FLT_MAX;
    for (int v = tid; v < Vv; v += 256) mx = fmaxf(mx, row[v]);
#pragma unroll
    for (int o = 16; o; o >>= 1) mx = fmaxf(mx, __shfl_xor_sync(~0u, mx, o));
    if ((tid & 31) == 0) sred[tid >> 5] = mx;
    __syncthreads();
    mx = sred[0];
#pragma unroll
    for (int i = 1; i < 8; i++) mx = fmaxf(mx, sred[i]);

    float s = 0.f;
    for (int v = tid; v < Vv; v += 256) s += __expf(row[v] - mx);
#pragma unroll
    for (int o = 16; o; o >>= 1) s += __shfl_xor_sync(~0u, s, o);
    __syncthreads();  // sred reuse
    if ((tid & 31) == 0) sred[tid >> 5] = s;
    __syncthreads();
    s = sred[0] + sred[1] + sred[2] + sred[3] + sred[4] + sred[5] + sred[6] + sred[7];

    float lse = mx + logf(s);
    for (int v = tid; v < Vv; v += 256) row[v] -= lse;
}

// ---------------- orchestration ----------------
extern "C" void kernel_launch(void* const* d_in, const int* in_sizes, int n_in,
                              void* d_out, int out_size)
{
    const float* enc  = (const float*)d_in[0];   // (B,S,H)
    const float* h0   = (const float*)d_in[1];   // (1,B,H)
    const int*   tgt  = (const int*)  d_in[2];   // (B,T)
    const float* emb  = (const float*)d_in[3];   // (V,H)
    const float* Wq   = (const float*)d_in[4];
    const float* Wk   = (const float*)d_in[5];
    const float* vat  = (const float*)d_in[6];
    const float* Wih  = (const float*)d_in[7];
    const float* Whh  = (const float*)d_in[8];
    const float* bih  = (const float*)d_in[9];
    const float* bhh  = (const float*)d_in[10];
    const float* Wout = (const float*)d_in[11];
    const float* bout = (const float*)d_in[12];

    float* out       = (float*)d_out;
    float* out_hT    = out + (size_t)Bb * Tt * Vv;
    float* out_attw  = out_hT + (size_t)Bb * Hh;

    (void)in_sizes; (void)n_in; (void)out_size;

    // Phase 1: kproj = enc @ Wk^T  (writes g_kproj internally; dst=nullptr)
    gemm_tn_kernel<<<dim3(Hh / 64, (Bb * Ss) / 64), 256>>>(
        enc, Wk, nullptr, nullptr, Bb * Ss, Hh, Hh, 0);
    init_h_kernel<<<(Bb * Hh + 255) / 256, 256>>>(h0);

    // Phase 2: sequential decode
    for (int t = 0; t < Tt; t++) {
        q_kernel<<<Hh / 16, 256>>>(Wq, t);
        scores_kernel<<<Bb * Ss, 128>>>(vat);
        ctx_kernel<<<dim3(Bb, 8), 128>>>(enc, out_attw, t);
        gru_kernel<<<Hh / 4, 256>>>(emb, tgt, Wih, Whh, bih, bhh, t);
    }

    copy_hT_kernel<<<(Bb * Hh + 255) / 256, 256>>>(out_hT);

    // Phase 3: logits = Hbuf @ Wout^T + bout (A=nullptr -> g_H+B*H; remap (t,b)->(b,t))
    gemm_tn_kernel<<<dim3(Vv / 64, (Bb * Tt) / 64), 256>>>(
        nullptr, Wout, bout, out, Bb * Tt, Vv, Hh, 1);
    logsoftmax_kernel<<<Bb * Tt, 256>>>(out);
}

// round 2
// speedup vs baseline: 1.2091x; 1.2091x over previous
#include <cuda_runtime.h>
#include <cuda_bf16.h>
#include <math.h>
#include <float.h>

#define Bb 16
#define Ss 128
#define Tt 128
#define Hh 1024
#define Vv 32000
#define BOSTOK 1

// ---------------- scratch (device globals; no allocs allowed) ----------------
__device__ float g_kproj[Bb * Ss * Hh];              // 8 MB
__device__ float g_H[(Tt + 1) * Bb * Hh];            // hidden states fp32
__device__ __nv_bfloat16 g_Hbf[Tt * Bb * Hh];        // h_{t+1} rows in bf16 (GEMM A)
__device__ __nv_bfloat16 g_Woutbf[(size_t)Vv * Hh];  // 64 MB bf16 copy of W_out
__device__ float g_q[Bb * Hh];
__device__ float g_scores[Bb * Ss];
__device__ float g_ctx[Bb * Hh];

// ---------------- math helpers ----------------
__device__ __forceinline__ float fast_tanh(float x) {
    float xc = fminf(fmaxf(x, -15.f), 15.f);
    float t = __expf(2.f * xc);
    return __fdividef(t - 1.f, t + 1.f);
}
__device__ __forceinline__ float fast_sigmoid(float x) {
    return __fdividef(1.f, 1.f + __expf(-x));
}

// ---------------- fp32 GEMM for kproj: C[m,n] = sum_k A[m,k]*B[n,k] --------
__global__ __launch_bounds__(256) void gemm_tn_kernel(
    const float* __restrict__ A, const float* __restrict__ Bw, int K)
{
    __shared__ float sA[16][64];
    __shared__ float sB[16][64];
    const int tid = threadIdx.x;
    const int bm = blockIdx.y * 64;
    const int bn = blockIdx.x * 64;
    const int lrow = tid >> 2;
    const int lk = (tid & 3) << 2;
    const int tx = tid & 15;
    const int ty = tid >> 4;

    const float* Ap = A + (size_t)(bm + lrow) * K + lk;
    const float* Bp = Bw + (size_t)(bn + lrow) * K + lk;

    float acc[4][4] = {};
    for (int k0 = 0; k0 < K; k0 += 16) {
        float4 av = *(const float4*)(Ap + k0);
        float4 bv = *(const float4*)(Bp + k0);
        sA[lk + 0][lrow] = av.x; sA[lk + 1][lrow] = av.y;
        sA[lk + 2][lrow] = av.z; sA[lk + 3][lrow] = av.w;
        sB[lk + 0][lrow] = bv.x; sB[lk + 1][lrow] = bv.y;
        sB[lk + 2][lrow] = bv.z; sB[lk + 3][lrow] = bv.w;
        __syncthreads();
#pragma unroll
        for (int kk = 0; kk < 16; kk++) {
            float4 a = *(const float4*)&sA[kk][ty << 2];
            float4 b = *(const float4*)&sB[kk][tx << 2];
            acc[0][0] = fmaf(a.x, b.x, acc[0][0]); acc[0][1] = fmaf(a.x, b.y, acc[0][1]);
            acc[0][2] = fmaf(a.x, b.z, acc[0][2]); acc[0][3] = fmaf(a.x, b.w, acc[0][3]);
            acc[1][0] = fmaf(a.y, b.x, acc[1][0]); acc[1][1] = fmaf(a.y, b.y, acc[1][1]);
            acc[1][2] = fmaf(a.y, b.z, acc[1][2]); acc[1][3] = fmaf(a.y, b.w, acc[1][3]);
            acc[2][0] = fmaf(a.z, b.x, acc[2][0]); acc[2][1] = fmaf(a.z, b.y, acc[2][1]);
            acc[2][2] = fmaf(a.z, b.z, acc[2][2]); acc[2][3] = fmaf(a.z, b.w, acc[2][3]);
            acc[3][0] = fmaf(a.w, b.x, acc[3][0]); acc[3][1] = fmaf(a.w, b.y, acc[3][1]);
            acc[3][2] = fmaf(a.w, b.z, acc[3][2]); acc[3][3] = fmaf(a.w, b.w, acc[3][3]);
        }
        __syncthreads();
    }
#pragma unroll
    for (int i = 0; i < 4; i++) {
        int m = bm + (ty << 2) + i;
        int n = bn + (tx << 2);
        *(float4*)(g_kproj + (size_t)m * Hh + n) =
            make_float4(acc[i][0], acc[i][1], acc[i][2], acc[i][3]);
    }
}

// ---------------- Wout -> bf16 conversion ----------------
__global__ __launch_bounds__(256) void conv_wout_kernel(const float* __restrict__ W)
{
    size_t n4 = (size_t)Vv * Hh / 4;
    uint2* dst = (uint2*)g_Woutbf;
    const float4* src = (const float4*)W;
    for (size_t i = blockIdx.x * 256 + threadIdx.x; i < n4; i += (size_t)gridDim.x * 256) {
        float4 v = src[i];
        __nv_bfloat162 lo = __floats2bfloat162_rn(v.x, v.y);
        __nv_bfloat162 hi = __floats2bfloat162_rn(v.z, v.w);
        uint2 o;
        o.x = *(const unsigned int*)&lo;
        o.y = *(const unsigned int*)&hi;
        dst[i] = o;
    }
}

// ---------------- h0 init / hT copy ----------------
__global__ void init_h_kernel(const float* __restrict__ h0) {
    int i = blockIdx.x * 256 + threadIdx.x;
    if (i < Bb * Hh) g_H[i] = h0[i];
}
__global__ void copy_hT_kernel(float* __restrict__ dst) {
    int i = blockIdx.x * 256 + threadIdx.x;
    if (i < Bb * Hh) dst[i] = g_H[(size_t)Tt * Bb * Hh + i];
}

// ---------------- per-step: q = h @ Wq^T ----------------
__global__ __launch_bounds__(256) void q_kernel(const float* __restrict__ Wq, int t)
{
    const float* h = g_H + (size_t)t * Bb * Hh;
    int m = threadIdx.x & 15;
    int n = blockIdx.x * 16 + (threadIdx.x >> 4);
    const float4* a = (const float4*)(h + (size_t)m * Hh);
    const float4* w = (const float4*)(Wq + (size_t)n * Hh);
    float acc = 0.f;
#pragma unroll 8
    for (int k = 0; k < Hh / 4; k++) {
        float4 av = a[k], wv = w[k];
        acc = fmaf(av.x, wv.x, acc); acc = fmaf(av.y, wv.y, acc);
        acc = fmaf(av.z, wv.z, acc); acc = fmaf(av.w, wv.w, acc);
    }
    g_q[m * Hh + n] = acc;
}

// ---------------- per-step: scores[b,s] = v . tanh(q[b]+kproj[b,s]) ----------
// 128 threads/block; thread owns 8 contiguous h (2 float4) -> independent tanh chains
__global__ __launch_bounds__(128) void scores_kernel(const float* __restrict__ v_att)
{
    int bs = blockIdx.x;
    int b = bs >> 7;
    int h0i = threadIdx.x * 8;
    const float4* qr = (const float4*)(g_q + (size_t)b * Hh + h0i);
    const float4* kp = (const float4*)(g_kproj + (size_t)bs * Hh + h0i);
    const float4* vp = (const float4*)(v_att + h0i);
    float acc = 0.f;
#pragma unroll
    for (int u = 0; u < 2; u++) {
        float4 q4 = qr[u], k4 = kp[u], v4 = vp[u];
        acc = fmaf(v4.x, fast_tanh(q4.x + k4.x), acc);
        acc = fmaf(v4.y, fast_tanh(q4.y + k4.y), acc);
        acc = fmaf(v4.z, fast_tanh(q4.z + k4.z), acc);
        acc = fmaf(v4.w, fast_tanh(q4.w + k4.w), acc);
    }
#pragma unroll
    for (int o = 16; o; o >>= 1) acc += __shfl_xor_sync(~0u, acc, o);
    __shared__ float sr[4];
    if ((threadIdx.x & 31) == 0) sr[threadIdx.x >> 5] = acc;
    __syncthreads();
    if (threadIdx.x == 0) g_scores[bs] = sr[0] + sr[1] + sr[2] + sr[3];
}

// ------- per-step: softmax over S (redundant per h-chunk) + ctx; store attw --
__global__ __launch_bounds__(128) void ctx_kernel(const float* __restrict__ enc,
                                                  float* __restrict__ attw, int t)
{
    int b = blockIdx.x, hc = blockIdx.y, tid = threadIdx.x;
    __shared__ float w[Ss];
    __shared__ float sred[4];

    float sc = g_scores[b * Ss + tid];
    float mx = sc;
#pragma unroll
    for (int o = 16; o; o >>= 1) mx = fmaxf(mx, __shfl_xor_sync(~0u, mx, o));
    if ((tid & 31) == 0) sred[tid >> 5] = mx;
    __syncthreads();
    mx = fmaxf(fmaxf(sred[0], sred[1]), fmaxf(sred[2], sred[3]));
    float e = __expf(sc - mx);
    float sm = e;
#pragma unroll
    for (int o = 16; o; o >>= 1) sm += __shfl_xor_sync(~0u, sm, o);
    __syncthreads();
    if ((tid & 31) == 0) sred[tid >> 5] = sm;
    __syncthreads();
    sm = sred[0] + sred[1] + sred[2] + sred[3];
    float wv = __fdividef(e, sm);
    w[tid] = wv;
    if (hc == 0) attw[((size_t)b * Tt + t) * Ss + tid] = wv;
    __syncthreads();

    int h = hc * 128 + tid;
    const float* ep = enc + ((size_t)b * Ss) * Hh + h;
    float acc = 0.f;
#pragma unroll 8
    for (int s = 0; s < Ss; s++) acc = fmaf(w[s], ep[(size_t)s * Hh], acc);
    g_ctx[b * Hh + h] = acc;
}

// ---------------- per-step: fused GRU gates + state update ----------------
__global__ __launch_bounds__(256) void gru_kernel(
    const float* __restrict__ emb, const int* __restrict__ tgt,
    const float* __restrict__ Wih, const float* __restrict__ Whh,
    const float* __restrict__ bih, const float* __restrict__ bhh, int t)
{
    const float* hprev = g_H + (size_t)t * Bb * Hh;
    float* hnew = g_H + (size_t)(t + 1) * Bb * Hh;
    int tid = threadIdx.x;
    int m = tid & 15;
    int jl = (tid >> 4) & 3;
    int kq = tid >> 6;
    int j = blockIdx.x * 4 + jl;

    int xi = (t == 0) ? BOSTOK : tgt[m * Tt + (t - 1)];
    const float* xsrc = (kq < 2) ? (emb + (size_t)xi * Hh + kq * 512)
                                 : (g_ctx + (size_t)m * Hh + (kq - 2) * 512);

    const float4* xs = (const float4*)xsrc;
    const float4* w0 = (const float4*)(Wih + (size_t)(0 * Hh + j) * (2 * Hh) + kq * 512);
    const float4* w1 = (const float4*)(Wih + (size_t)(1 * Hh + j) * (2 * Hh) + kq * 512);
    const float4* w2 = (const float4*)(Wih + (size_t)(2 * Hh + j) * (2 * Hh) + kq * 512);
    float a0 = 0.f, a1 = 0.f, a2 = 0.f;
#pragma unroll 4
    for (int i = 0; i < 128; i++) {
        float4 x = xs[i];
        float4 u = w0[i];
        a0 = fmaf(x.x, u.x, a0); a0 = fmaf(x.y, u.y, a0); a0 = fmaf(x.z, u.z, a0); a0 = fmaf(x.w, u.w, a0);
        float4 v = w1[i];
        a1 = fmaf(x.x, v.x, a1); a1 = fmaf(x.y, v.y, a1); a1 = fmaf(x.z, v.z, a1); a1 = fmaf(x.w, v.w, a1);
        float4 q = w2[i];
        a2 = fmaf(x.x, q.x, a2); a2 = fmaf(x.y, q.y, a2); a2 = fmaf(x.z, q.z, a2); a2 = fmaf(x.w, q.w, a2);
    }

    const float4* hs = (const float4*)(hprev + (size_t)m * Hh + kq * 256);
    const float4* v0 = (const float4*)(Whh + (size_t)(0 * Hh + j) * Hh + kq * 256);
    const float4* v1 = (const float4*)(Whh + (size_t)(1 * Hh + j) * Hh + kq * 256);
    const float4* v2 = (const float4*)(Whh + (size_t)(2 * Hh + j) * Hh + kq * 256);
    float b0 = 0.f, b1 = 0.f, b2 = 0.f;
#pragma unroll 4
    for (int i = 0; i < 64; i++) {
        float4 x = hs[i];
        float4 u = v0[i];
        b0 = fmaf(x.x, u.x, b0); b0 = fmaf(x.y, u.y, b0); b0 = fmaf(x.z, u.z, b0); b0 = fmaf(x.w, u.w, b0);
        float4 v = v1[i];
        b1 = fmaf(x.x, v.x, b1); b1 = fmaf(x.y, v.y, b1); b1 = fmaf(x.z, v.z, b1); b1 = fmaf(x.w, v.w, b1);
        float4 q = v2[i];
        b2 = fmaf(x.x, q.x, b2); b2 = fmaf(x.y, q.y, b2); b2 = fmaf(x.z, q.z, b2); b2 = fmaf(x.w, q.w, b2);
    }

    __shared__ float red[4][64][6];
    int sl = jl * 16 + m;
    red[kq][sl][0] = a0; red[kq][sl][1] = a1; red[kq][sl][2] = a2;
    red[kq][sl][3] = b0; red[kq][sl][4] = b1; red[kq][sl][5] = b2;
    __syncthreads();
    if (kq == 0) {
        float gx0 = red[0][sl][0] + red[1][sl][0] + red[2][sl][0] + red[3][sl][0] + bih[j];
        float gx1 = red[0][sl][1] + red[1][sl][1] + red[2][sl][1] + red[3][sl][1] + bih[Hh + j];
        float gx2 = red[0][sl][2] + red[1][sl][2] + red[2][sl][2] + red[3][sl][2] + bih[2 * Hh + j];
        float gh0 = red[0][sl][3] + red[1][sl][3] + red[2][sl][3] + red[3][sl][3] + bhh[j];
        float gh1 = red[0][sl][4] + red[1][sl][4] + red[2][sl][4] + red[3][sl][4] + bhh[Hh + j];
        float gh2 = red[0][sl][5] + red[1][sl][5] + red[2][sl][5] + red[3][sl][5] + bhh[2 * Hh + j];
        float r = fast_sigmoid(gx0 + gh0);
        float z = fast_sigmoid(gx1 + gh1);
        float n = fast_tanh(gx2 + r * gh2);
        float hp = hprev[m * Hh + j];
        float hv = (1.f - z) * n + z * hp;
        hnew[m * Hh + j] = hv;
        g_Hbf[((size_t)t * Bb + m) * Hh + j] = __float2bfloat16(hv);
    }
}

// -------- logits: bf16 tensor-core GEMM, out[(b*T+t)][v] = Hbf[t*16+b] . Wout[v] + bias --
// BM=128, BN=64, BK=32; 256 threads = 8 warps (4 m x 2 n), warp tile 32x32.
__device__ __forceinline__ void mma16816(float* c, unsigned int a0, unsigned int a1,
                                         unsigned int a2, unsigned int a3,
                                         unsigned int b0, unsigned int b1)
{
    asm volatile(
        "mma.sync.aligned.m16n8k16.row.col.f32.bf16.bf16.f32 "
        "{%0,%1,%2,%3}, {%4,%5,%6,%7}, {%8,%9}, {%0,%1,%2,%3};\n"
        : "+f"(c[0]), "+f"(c[1]), "+f"(c[2]), "+f"(c[3])
        : "r"(a0), "r"(a1), "r"(a2), "r"(a3), "r"(b0), "r"(b1));
}

__global__ __launch_bounds__(256) void logits_mma_kernel(
    const float* __restrict__ bout, float* __restrict__ out)
{
    __shared__ __nv_bfloat16 sA[128][40];
    __shared__ __nv_bfloat16 sB[64][40];

    const int tid = threadIdx.x;
    const int warp = tid >> 5;
    const int lane = tid & 31;
    const int wm = (warp & 3) * 32;
    const int wn = (warp >> 2) * 32;
    const int bm = blockIdx.y * 128;
    const int bn = blockIdx.x * 64;

    const int lr = tid >> 2;           // 0..63
    const int lc = (tid & 3) * 8;      // 0,8,16,24

    const __nv_bfloat16* Abase = g_Hbf + (size_t)(bm + lr) * Hh + lc;
    const __nv_bfloat16* A2base = g_Hbf + (size_t)(bm + lr + 64) * Hh + lc;
    const __nv_bfloat16* Bbase = g_Woutbf + (size_t)(bn + lr) * Hh + lc;

    float acc[2][4][4] = {};
    const int row = lane >> 2;
    const int kc = (lane & 3) * 2;

    for (int k0 = 0; k0 < Hh; k0 += 32) {
        *(uint4*)&sA[lr][lc]      = *(const uint4*)(Abase + k0);
        *(uint4*)&sA[lr + 64][lc] = *(const uint4*)(A2base + k0);
        *(uint4*)&sB[lr][lc]      = *(const uint4*)(Bbase + k0);
        __syncthreads();
#pragma unroll
        for (int kk = 0; kk < 32; kk += 16) {
            unsigned int a[2][4], b[4][2];
#pragma unroll
            for (int mf = 0; mf < 2; mf++) {
                int r0 = wm + mf * 16 + row;
                a[mf][0] = *(const unsigned int*)&sA[r0][kk + kc];
                a[mf][1] = *(const unsigned int*)&sA[r0 + 8][kk + kc];
                a[mf][2] = *(const unsigned int*)&sA[r0][kk + kc + 8];
                a[mf][3] = *(const unsigned int*)&sA[r0 + 8][kk + kc + 8];
            }
#pragma unroll
            for (int nf = 0; nf < 4; nf++) {
                int r0 = wn + nf * 8 + row;
                b[nf][0] = *(const unsigned int*)&sB[r0][kk + kc];
                b[nf][1] = *(const unsigned int*)&sB[r0][kk + kc + 8];
            }
#pragma unroll
            for (int mf = 0; mf < 2; mf++)
#pragma unroll
                for (int nf = 0; nf < 4; nf++)
                    mma16816(acc[mf][nf], a[mf][0], a[mf][1], a[mf][2], a[mf][3],
                             b[nf][0], b[nf][1]);
        }
        __syncthreads();
    }

    // epilogue: remap GEMM row R = t*16+b  ->  output row b*128+t
#pragma unroll
    for (int mf = 0; mf < 2; mf++) {
#pragma unroll
        for (int nf = 0; nf < 4; nf++) {
            int gm = bm + wm + mf * 16 + row;
            int gn = bn + wn + nf * 8 + kc;
            float bi0 = bout[gn], bi1 = bout[gn + 1];
            int o0 = (gm & 15) * Tt + (gm >> 4);
            *(float2*)(out + (size_t)o0 * Vv + gn) =
                make_float2(acc[mf][nf][0] + bi0, acc[mf][nf][1] + bi1);
            int gm2 = gm + 8;
            int o1 = (gm2 & 15) * Tt + (gm2 >> 4);
            *(float2*)(out + (size_t)o1 * Vv + gn) =
                make_float2(acc[mf][nf][2] + bi0, acc[mf][nf][3] + bi1);
        }
    }
}

// ---------------- final: in-place log_softmax over V per (b,t) row -----------
__global__ __launch_bounds__(256) void logsoftmax_kernel(float* __restrict__ out)
{
    float* row = out + (size_t)blockIdx.x * Vv;
    int tid = threadIdx.x;
    __shared__ float sred[8];

    float mx = -FLT_MAX;
    for (int v = tid; v < Vv; v += 256) mx = fmaxf(mx, row[v]);
#pragma unroll
    for (int o = 16; o; o >>= 1) mx = fmaxf(mx, __shfl_xor_sync(~0u, mx, o));
    if ((tid & 31) == 0) sred[tid >> 5] = mx;
    __syncthreads();
    mx = sred[0];
#pragma unroll
    for (int i = 1; i < 8; i++) mx = fmaxf(mx, sred[i]);

    float s = 0.f;
    for (int v = tid; v < Vv; v += 256) s += __expf(row[v] - mx);
#pragma unroll
    for (int o = 16; o; o >>= 1) s += __shfl_xor_sync(~0u, s, o);
    __syncthreads();
    if ((tid & 31) == 0) sred[tid >> 5] = s;
    __syncthreads();
    s = sred[0] + sred[1] + sred[2] + sred[3] + sred[4] + sred[5] + sred[6] + sred[7];

    float lse = mx + logf(s);
    for (int v = tid; v < Vv; v += 256) row[v] -= lse;
}

// ---------------- orchestration ----------------
extern "C" void kernel_launch(void* const* d_in, const int* in_sizes, int n_in,
                              void* d_out, int out_size)
{
    const float* enc  = (const float*)d_in[0];
    const float* h0   = (const float*)d_in[1];
    const int*   tgt  = (const int*)  d_in[2];
    const float* emb  = (const float*)d_in[3];
    const float* Wq   = (const float*)d_in[4];
    const float* Wk   = (const float*)d_in[5];
    const float* vat  = (const float*)d_in[6];
    const float* Wih  = (const float*)d_in[7];
    const float* Whh  = (const float*)d_in[8];
    const float* bih  = (const float*)d_in[9];
    const float* bhh  = (const float*)d_in[10];
    const float* Wout = (const float*)d_in[11];
    const float* bout = (const float*)d_in[12];

    float* out       = (float*)d_out;
    float* out_hT    = out + (size_t)Bb * Tt * Vv;
    float* out_attw  = out_hT + (size_t)Bb * Hh;

    (void)in_sizes; (void)n_in; (void)out_size;

    // Phase 0: one-time conversions + kproj
    conv_wout_kernel<<<4096, 256>>>(Wout);
    gemm_tn_kernel<<<dim3(Hh / 64, (Bb * Ss) / 64), 256>>>(enc, Wk, Hh);
    init_h_kernel<<<(Bb * Hh + 255) / 256, 256>>>(h0);

    // Phase 2: sequential decode
    for (int t = 0; t < Tt; t++) {
        q_kernel<<<Hh / 16, 256>>>(Wq, t);
        scores_kernel<<<Bb * Ss, 128>>>(vat);
        ctx_kernel<<<dim3(Bb, 8), 128>>>(enc, out_attw, t);
        gru_kernel<<<Hh / 4, 256>>>(emb, tgt, Wih, Whh, bih, bhh, t);
    }

    copy_hT_kernel<<<(Bb * Hh + 255) / 256, 256>>>(out_hT);

    // Phase 3: logits on tensor cores (bf16 x bf16 -> fp32) + log_softmax
    logits_mma_kernel<<<dim3(Vv / 64, (Bb * Tt) / 128), 256>>>(bout, out);
    logsoftmax_kernel<<<Bb * Tt, 256>>>(out);
}

// round 3
// speedup vs baseline: 3.4031x; 2.8146x over previous
#include <cuda_runtime.h>
#include <cuda_bf16.h>
#include <math.h>
#include <float.h>

#define Bb 16
#define Ss 128
#define Tt 128
#define Hh 1024
#define Vv 32000
#define BOSTOK 1

// ---------------- scratch (device globals; no allocs allowed) ----------------
__device__ float g_kproj[Bb * Ss * Hh];                 // 8 MB
__device__ float g_H[(Tt + 1) * Bb * Hh];               // hidden states fp32
__device__ __nv_bfloat16 g_Hbf[Tt * Bb * Hh];           // h_{t+1} rows bf16 (logits A)
__device__ __nv_bfloat16 g_Woutbf[(size_t)Vv * Hh];     // 64 MB bf16 W_out
__device__ __nv_bfloat16 g_embbf[Tt * Bb * Hh];         // gathered dec-in embeddings bf16
__device__ __nv_bfloat16 g_Wihembbf[3 * Hh * Hh];       // Wih[:, :H] bf16
__device__ float g_gxemb[Tt * Bb * 3 * Hh];             // 25 MB: emb-part gate preacts (+bih)
__device__ float g_q[Bb * Hh];
__device__ float g_gh[Bb * 3 * Hh];                     // h-part gate preacts (+bhh)
__device__ float g_scores[Bb * Ss];
__device__ float g_ctx[Bb * Hh];

// ---------------- math helpers ----------------
__device__ __forceinline__ float fast_tanh(float x) {
    float xc = fminf(fmaxf(x, -15.f), 15.f);
    float t = __expf(2.f * xc);
    return __fdividef(t - 1.f, t + 1.f);
}
__device__ __forceinline__ float fast_sigmoid(float x) {
    return __fdividef(1.f, 1.f + __expf(-x));
}

// ---------------- fp32 GEMM for kproj: C[m,n] = sum_k A[m,k]*B[n,k] --------
__global__ __launch_bounds__(256) void gemm_tn_kernel(
    const float* __restrict__ A, const float* __restrict__ Bw, int K)
{
    __shared__ float sA[16][64];
    __shared__ float sB[16][64];
    const int tid = threadIdx.x;
    const int bm = blockIdx.y * 64;
    const int bn = blockIdx.x * 64;
    const int lrow = tid >> 2;
    const int lk = (tid & 3) << 2;
    const int tx = tid & 15;
    const int ty = tid >> 4;

    const float* Ap = A + (size_t)(bm + lrow) * K + lk;
    const float* Bp = Bw + (size_t)(bn + lrow) * K + lk;

    float acc[4][4] = {};
    for (int k0 = 0; k0 < K; k0 += 16) {
        float4 av = *(const float4*)(Ap + k0);
        float4 bv = *(const float4*)(Bp + k0);
        sA[lk + 0][lrow] = av.x; sA[lk + 1][lrow] = av.y;
        sA[lk + 2][lrow] = av.z; sA[lk + 3][lrow] = av.w;
        sB[lk + 0][lrow] = bv.x; sB[lk + 1][lrow] = bv.y;
        sB[lk + 2][lrow] = bv.z; sB[lk + 3][lrow] = bv.w;
        __syncthreads();
#pragma unroll
        for (int kk = 0; kk < 16; kk++) {
            float4 a = *(const float4*)&sA[kk][ty << 2];
            float4 b = *(const float4*)&sB[kk][tx << 2];
            acc[0][0] = fmaf(a.x, b.x, acc[0][0]); acc[0][1] = fmaf(a.x, b.y, acc[0][1]);
            acc[0][2] = fmaf(a.x, b.z, acc[0][2]); acc[0][3] = fmaf(a.x, b.w, acc[0][3]);
            acc[1][0] = fmaf(a.y, b.x, acc[1][0]); acc[1][1] = fmaf(a.y, b.y, acc[1][1]);
            acc[1][2] = fmaf(a.y, b.z, acc[1][2]); acc[1][3] = fmaf(a.y, b.w, acc[1][3]);
            acc[2][0] = fmaf(a.z, b.x, acc[2][0]); acc[2][1] = fmaf(a.z, b.y, acc[2][1]);
            acc[2][2] = fmaf(a.z, b.z, acc[2][2]); acc[2][3] = fmaf(a.z, b.w, acc[2][3]);
            acc[3][0] = fmaf(a.w, b.x, acc[3][0]); acc[3][1] = fmaf(a.w, b.y, acc[3][1]);
            acc[3][2] = fmaf(a.w, b.z, acc[3][2]); acc[3][3] = fmaf(a.w, b.w, acc[3][3]);
        }
        __syncthreads();
    }
#pragma unroll
    for (int i = 0; i < 4; i++) {
        int m = bm + (ty << 2) + i;
        int n = bn + (tx << 2);
        *(float4*)(g_kproj + (size_t)m * Hh + n) =
            make_float4(acc[i][0], acc[i][1], acc[i][2], acc[i][3]);
    }
}

// ---------------- one-time conversions / gathers ----------------
__global__ __launch_bounds__(256) void conv_wout_kernel(const float* __restrict__ W)
{
    size_t n4 = (size_t)Vv * Hh / 4;
    uint2* dst = (uint2*)g_Woutbf;
    const float4* src = (const float4*)W;
    for (size_t i = blockIdx.x * 256 + threadIdx.x; i < n4; i += (size_t)gridDim.x * 256) {
        float4 v = src[i];
        __nv_bfloat162 lo = __floats2bfloat162_rn(v.x, v.y);
        __nv_bfloat162 hi = __floats2bfloat162_rn(v.z, v.w);
        uint2 o;
        o.x = *(const unsigned int*)&lo;
        o.y = *(const unsigned int*)&hi;
        dst[i] = o;
    }
}

// Wih[:, :H] -> bf16 (row j of 3072, first 1024 cols; Wih row stride 2048)
__global__ __launch_bounds__(256) void conv_wihemb_kernel(const float* __restrict__ Wih)
{
    int j = blockIdx.x;                 // 0..3071
    int c = threadIdx.x * 4;            // 0..1020
    float4 v = *(const float4*)(Wih + (size_t)j * (2 * Hh) + c);
    __nv_bfloat162 lo = __floats2bfloat162_rn(v.x, v.y);
    __nv_bfloat162 hi = __floats2bfloat162_rn(v.z, v.w);
    uint2 o;
    o.x = *(const unsigned int*)&lo;
    o.y = *(const unsigned int*)&hi;
    *(uint2*)(g_Wihembbf + (size_t)j * Hh + c) = o;
}

// gather A rows for emb GEMM: row r = t*16+b  -> emb[dec_in[b,t]] in bf16
__global__ __launch_bounds__(256) void gather_emb_kernel(
    const float* __restrict__ emb, const int* __restrict__ tgt)
{
    int r = blockIdx.x;                 // 0..2047
    int t = r >> 4, b = r & 15;
    int tok = (t == 0) ? BOSTOK : tgt[b * Tt + (t - 1)];
    int c = threadIdx.x * 4;
    float4 v = *(const float4*)(emb + (size_t)tok * Hh + c);
    __nv_bfloat162 lo = __floats2bfloat162_rn(v.x, v.y);
    __nv_bfloat162 hi = __floats2bfloat162_rn(v.z, v.w);
    uint2 o;
    o.x = *(const unsigned int*)&lo;
    o.y = *(const unsigned int*)&hi;
    *(uint2*)(g_embbf + (size_t)r * Hh + c) = o;
}

// ---------------- h0 init / hT copy ----------------
__global__ void init_h_kernel(const float* __restrict__ h0) {
    int i = blockIdx.x * 256 + threadIdx.x;
    if (i < Bb * Hh) g_H[i] = h0[i];
}
__global__ void copy_hT_kernel(float* __restrict__ dst) {
    int i = blockIdx.x * 256 + threadIdx.x;
    if (i < Bb * Hh) dst[i] = g_H[(size_t)Tt * Bb * Hh + i];
}

// ---------------- bf16 tensor-core GEMM (K=1024 fixed) ----------------
// out[row][n] = A[gm] . B[n] + bias[n];  row = remap ? (b*T+t from gm=t*16+b) : gm
__device__ __forceinline__ void mma16816(float* c, unsigned int a0, unsigned int a1,
                                         unsigned int a2, unsigned int a3,
                                         unsigned int b0, unsigned int b1)
{
    asm volatile(
        "mma.sync.aligned.m16n8k16.row.col.f32.bf16.bf16.f32 "
        "{%0,%1,%2,%3}, {%4,%5,%6,%7}, {%8,%9}, {%0,%1,%2,%3};\n"
        : "+f"(c[0]), "+f"(c[1]), "+f"(c[2]), "+f"(c[3])
        : "r"(a0), "r"(a1), "r"(a2), "r"(a3), "r"(b0), "r"(b1));
}

__global__ __launch_bounds__(256) void bf16_mma_kernel(
    const __nv_bfloat16* __restrict__ A, const __nv_bfloat16* __restrict__ Bm,
    const float* __restrict__ bias, float* __restrict__ out, int N, int remap)
{
    __shared__ __nv_bfloat16 sA[128][40];
    __shared__ __nv_bfloat16 sB[64][40];

    const int tid = threadIdx.x;
    const int warp = tid >> 5;
    const int lane = tid & 31;
    const int wm = (warp & 3) * 32;
    const int wn = (warp >> 2) * 32;
    const int bm = blockIdx.y * 128;
    const int bn = blockIdx.x * 64;

    const int lr = tid >> 2;
    const int lc = (tid & 3) * 8;

    const __nv_bfloat16* Abase = A + (size_t)(bm + lr) * Hh + lc;
    const __nv_bfloat16* A2base = A + (size_t)(bm + lr + 64) * Hh + lc;
    const __nv_bfloat16* Bbase = Bm + (size_t)(bn + lr) * Hh + lc;

    float acc[2][4][4] = {};
    const int row = lane >> 2;
    const int kc = (lane & 3) * 2;

    for (int k0 = 0; k0 < Hh; k0 += 32) {
        *(uint4*)&sA[lr][lc]      = *(const uint4*)(Abase + k0);
        *(uint4*)&sA[lr + 64][lc] = *(const uint4*)(A2base + k0);
        *(uint4*)&sB[lr][lc]      = *(const uint4*)(Bbase + k0);
        __syncthreads();
#pragma unroll
        for (int kk = 0; kk < 32; kk += 16) {
            unsigned int a[2][4], b[4][2];
#pragma unroll
            for (int mf = 0; mf < 2; mf++) {
                int r0 = wm + mf * 16 + row;
                a[mf][0] = *(const unsigned int*)&sA[r0][kk + kc];
                a[mf][1] = *(const unsigned int*)&sA[r0 + 8][kk + kc];
                a[mf][2] = *(const unsigned int*)&sA[r0][kk + kc + 8];
                a[mf][3] = *(const unsigned int*)&sA[r0 + 8][kk + kc + 8];
            }
#pragma unroll
            for (int nf = 0; nf < 4; nf++) {
                int r0 = wn + nf * 8 + row;
                b[nf][0] = *(const unsigned int*)&sB[r0][kk + kc];
                b[nf][1] = *(const unsigned int*)&sB[r0][kk + kc + 8];
            }
#pragma unroll
            for (int mf = 0; mf < 2; mf++)
#pragma unroll
                for (int nf = 0; nf < 4; nf++)
                    mma16816(acc[mf][nf], a[mf][0], a[mf][1], a[mf][2], a[mf][3],
                             b[nf][0], b[nf][1]);
        }
        __syncthreads();
    }

#pragma unroll
    for (int mf = 0; mf < 2; mf++) {
#pragma unroll
        for (int nf = 0; nf < 4; nf++) {
            int gm = bm + wm + mf * 16 + row;
            int gn = bn + wn + nf * 8 + kc;
            float bi0 = bias[gn], bi1 = bias[gn + 1];
            int o0 = remap ? ((gm & 15) * Tt + (gm >> 4)) : gm;
            *(float2*)(out + (size_t)o0 * N + gn) =
                make_float2(acc[mf][nf][0] + bi0, acc[mf][nf][1] + bi1);
            int gm2 = gm + 8;
            int o1 = remap ? ((gm2 & 15) * Tt + (gm2 >> 4)) : gm2;
            *(float2*)(out + (size_t)o1 * N + gn) =
                make_float2(acc[mf][nf][2] + bi0, acc[mf][nf][3] + bi1);
        }
    }
}

// ---------------- per-step: [q | gh] = h @ [Wq; Whh]^T (+bhh on gh rows) ------
// grid 256 blocks x 256 threads, dynamic smem: h 16x1024 fp32 (64 KB)
__global__ __launch_bounds__(256) void hgemm_kernel(
    const float* __restrict__ Wq, const float* __restrict__ Whh,
    const float* __restrict__ bhh, int t)
{
    extern __shared__ float sh[];
    const int tid = threadIdx.x;
    const float4* hsrc = (const float4*)(g_H + (size_t)t * Bb * Hh);
#pragma unroll
    for (int i = tid; i < Bb * Hh / 4; i += 256) ((float4*)sh)[i] = hsrc[i];
    __syncthreads();

    const int nl = tid & 15;
    const int kq = tid >> 4;            // 0..15, K-chunk of 64
    const int r = blockIdx.x * 16 + nl; // 0..4095
    const float* wrow = (r < Hh) ? (Wq + (size_t)r * Hh)
                                 : (Whh + (size_t)(r - Hh) * Hh);
    const float4* w4 = (const float4*)(wrow + kq * 64);
    const float* hb = sh + kq * 64;

    float acc[16] = {};
#pragma unroll
    for (int i = 0; i < 16; i++) {
        float4 w = w4[i];
#pragma unroll
        for (int m = 0; m < 16; m++) {
            float4 hv = *(const float4*)(hb + m * Hh + i * 4);
            acc[m] = fmaf(w.x, hv.x, acc[m]);
            acc[m] = fmaf(w.y, hv.y, acc[m]);
            acc[m] = fmaf(w.z, hv.z, acc[m]);
            acc[m] = fmaf(w.w, hv.w, acc[m]);
        }
    }
    __syncthreads();                    // h reads done; overlay reduction
    float* red = sh;                    // [nl][m][kq] : 16*16*16
#pragma unroll
    for (int m = 0; m < 16; m++) red[(nl * 16 + m) * 16 + kq] = acc[m];
    __syncthreads();

    const int nl2 = tid >> 4, m2 = tid & 15;
    float s = 0.f;
#pragma unroll
    for (int k = 0; k < 16; k++) s += red[(nl2 * 16 + m2) * 16 + k];
    int r2 = blockIdx.x * 16 + nl2;
    if (r2 < Hh) g_q[m2 * Hh + r2] = s;
    else         g_gh[m2 * 3 * Hh + (r2 - Hh)] = s + bhh[r2 - Hh];
}

// ---------------- per-step: scores[b,s] = v . tanh(q[b]+kproj[b,s]) ----------
__global__ __launch_bounds__(128) void scores_kernel(const float* __restrict__ v_att)
{
    int bs = blockIdx.x;
    int b = bs >> 7;
    int h0i = threadIdx.x * 8;
    const float4* qr = (const float4*)(g_q + (size_t)b * Hh + h0i);
    const float4* kp = (const float4*)(g_kproj + (size_t)bs * Hh + h0i);
    const float4* vp = (const float4*)(v_att + h0i);
    float acc = 0.f;
#pragma unroll
    for (int u = 0; u < 2; u++) {
        float4 q4 = qr[u], k4 = kp[u], v4 = vp[u];
        acc = fmaf(v4.x, fast_tanh(q4.x + k4.x), acc);
        acc = fmaf(v4.y, fast_tanh(q4.y + k4.y), acc);
        acc = fmaf(v4.z, fast_tanh(q4.z + k4.z), acc);
        acc = fmaf(v4.w, fast_tanh(q4.w + k4.w), acc);
    }
#pragma unroll
    for (int o = 16; o; o >>= 1) acc += __shfl_xor_sync(~0u, acc, o);
    __shared__ float sr[4];
    if ((threadIdx.x & 31) == 0) sr[threadIdx.x >> 5] = acc;
    __syncthreads();
    if (threadIdx.x == 0) g_scores[bs] = sr[0] + sr[1] + sr[2] + sr[3];
}

// ------- per-step: softmax over S + ctx; store attw --------------------------
__global__ __launch_bounds__(128) void ctx_kernel(const float* __restrict__ enc,
                                                  float* __restrict__ attw, int t)
{
    int b = blockIdx.x, hc = blockIdx.y, tid = threadIdx.x;
    __shared__ float w[Ss];
    __shared__ float sred[4];

    float sc = g_scores[b * Ss + tid];
    float mx = sc;
#pragma unroll
    for (int o = 16; o; o >>= 1) mx = fmaxf(mx, __shfl_xor_sync(~0u, mx, o));
    if ((tid & 31) == 0) sred[tid >> 5] = mx;
    __syncthreads();
    mx = fmaxf(fmaxf(sred[0], sred[1]), fmaxf(sred[2], sred[3]));
    float e = __expf(sc - mx);
    float sm = e;
#pragma unroll
    for (int o = 16; o; o >>= 1) sm += __shfl_xor_sync(~0u, sm, o);
    __syncthreads();
    if ((tid & 31) == 0) sred[tid >> 5] = sm;
    __syncthreads();
    sm = sred[0] + sred[1] + sred[2] + sred[3];
    float wv = __fdividef(e, sm);
    w[tid] = wv;
    if (hc == 0) attw[((size_t)b * Tt + t) * Ss + tid] = wv;
    __syncthreads();

    int h = hc * 128 + tid;
    const float* ep = enc + ((size_t)b * Ss) * Hh + h;
    float acc = 0.f;
#pragma unroll 8
    for (int s = 0; s < Ss; s++) acc = fmaf(w[s], ep[(size_t)s * Hh], acc);
    g_ctx[b * Hh + h] = acc;
}

// ------- per-step: gx_ctx = ctx @ Wih[:, H:2H]^T, fused with gate update -----
// grid 256 blocks x 192 threads; dynamic smem: ctx 16x1024 fp32 (64 KB)
__global__ __launch_bounds__(192) void gru2_kernel(const float* __restrict__ Wih, int t)
{
    extern __shared__ float sh[];
    const int tid = threadIdx.x;
    const float4* csrc = (const float4*)g_ctx;
    for (int i = tid; i < Bb * Hh / 4; i += 192) ((float4*)sh)[i] = csrc[i];
    __syncthreads();

    const int jl = tid & 3;
    const int rest = tid >> 2;
    const int g = rest % 3;
    const int kq = rest / 3;            // 0..15
    const int j = blockIdx.x * 4 + jl;  // 0..1023

    const float* wrow = Wih + (size_t)(g * Hh + j) * (2 * Hh) + Hh + kq * 64;
    const float4* w4 = (const float4*)wrow;
    const float* cb = sh + kq * 64;

    float acc[16] = {};
#pragma unroll
    for (int i = 0; i < 16; i++) {
        float4 w = w4[i];
#pragma unroll
        for (int m = 0; m < 16; m++) {
            float4 cv = *(const float4*)(cb + m * Hh + i * 4);
            acc[m] = fmaf(w.x, cv.x, acc[m]);
            acc[m] = fmaf(w.y, cv.y, acc[m]);
            acc[m] = fmaf(w.z, cv.z, acc[m]);
            acc[m] = fmaf(w.w, cv.w, acc[m]);
        }
    }
    __syncthreads();
    float* red = sh;                    // [jl][g][m][kq] : 4*3*16*16
#pragma unroll
    for (int m = 0; m < 16; m++)
        red[(((jl * 3 + g) * 16) + m) * 16 + kq] = acc[m];
    __syncthreads();

    if (tid < 64) {
        const int jl2 = tid & 3;
        const int m2 = tid >> 2;        // batch index
        const int j2 = blockIdx.x * 4 + jl2;
        float gs[3];
#pragma unroll
        for (int gg = 0; gg < 3; gg++) {
            float s = 0.f;
#pragma unroll
            for (int k = 0; k < 16; k++)
                s += red[(((jl2 * 3 + gg) * 16) + m2) * 16 + k];
            gs[gg] = s;
        }
        const int r = t * Bb + m2;
        const float* gxe = g_gxemb + (size_t)r * 3 * Hh;
        const float* ghp = g_gh + (size_t)m2 * 3 * Hh;
        float gx_r = gxe[j2]          + gs[0];
        float gx_z = gxe[Hh + j2]     + gs[1];
        float gx_n = gxe[2 * Hh + j2] + gs[2];
        float gh_r = ghp[j2];
        float gh_z = ghp[Hh + j2];
        float gh_n = ghp[2 * Hh + j2];
        float rg = fast_sigmoid(gx_r + gh_r);
        float z  = fast_sigmoid(gx_z + gh_z);
        float nn = fast_tanh(gx_n + rg * gh_n);
        float hp = g_H[(size_t)t * Bb * Hh + m2 * Hh + j2];
        float hv = (1.f - z) * nn + z * hp;
        g_H[(size_t)(t + 1) * Bb * Hh + m2 * Hh + j2] = hv;
        g_Hbf[(size_t)r * Hh + j2] = __float2bfloat16(hv);
    }
}

// ---------------- final: in-place log_softmax over V per (b,t) row -----------
__global__ __launch_bounds__(256) void logsoftmax_kernel(float* __restrict__ out)
{
    float* row = out + (size_t)blockIdx.x * Vv;
    int tid = threadIdx.x;
    __shared__ float sred[8];

    float mx = -FLT_MAX;
    for (int v = tid; v < Vv; v += 256) mx = fmaxf(mx, row[v]);
#pragma unroll
    for (int o = 16; o; o >>= 1) mx = fmaxf(mx, __shfl_xor_sync(~0u, mx, o));
    if ((tid & 31) == 0) sred[tid >> 5] = mx;
    __syncthreads();
    mx = sred[0];
#pragma unroll
    for (int i = 1; i < 8; i++) mx = fmaxf(mx, sred[i]);

    float s = 0.f;
    for (int v = tid; v < Vv; v += 256) s += __expf(row[v] - mx);
#pragma unroll
    for (int o = 16; o; o >>= 1) s += __shfl_xor_sync(~0u, s, o);
    __syncthreads();
    if ((tid & 31) == 0) sred[tid >> 5] = s;
    __syncthreads();
    s = sred[0] + sred[1] + sred[2] + sred[3] + sred[4] + sred[5] + sred[6] + sred[7];

    float lse = mx + logf(s);
    for (int v = tid; v < Vv; v += 256) row[v] -= lse;
}

// ---------------- orchestration ----------------
extern "C" void kernel_launch(void* const* d_in, const int* in_sizes, int n_in,
                              void* d_out, int out_size)
{
    const float* enc  = (const float*)d_in[0];
    const float* h0   = (const float*)d_in[1];
    const int*   tgt  = (const int*)  d_in[2];
    const float* emb  = (const float*)d_in[3];
    const float* Wq   = (const float*)d_in[4];
    const float* Wk   = (const float*)d_in[5];
    const float* vat  = (const float*)d_in[6];
    const float* Wih  = (const float*)d_in[7];
    const float* Whh  = (const float*)d_in[8];
    const float* bih  = (const float*)d_in[9];
    const float* bhh  = (const float*)d_in[10];
    const float* Wout = (const float*)d_in[11];
    const float* bout = (const float*)d_in[12];

    float* out       = (float*)d_out;
    float* out_hT    = out + (size_t)Bb * Tt * Vv;
    float* out_attw  = out_hT + (size_t)Bb * Hh;

    (void)in_sizes; (void)n_in; (void)out_size;

    cudaFuncSetAttribute(hgemm_kernel, cudaFuncAttributeMaxDynamicSharedMemorySize, 65536);
    cudaFuncSetAttribute(gru2_kernel,  cudaFuncAttributeMaxDynamicSharedMemorySize, 65536);

    // Phase 0: one-time conversions / precomputes
    conv_wout_kernel<<<4096, 256>>>(Wout);
    conv_wihemb_kernel<<<3 * Hh, 256>>>(Wih);
    gather_emb_kernel<<<Tt * Bb, 256>>>(emb, tgt);
    float* gxemb_ptr; cudaGetSymbolAddress((void**)&gxemb_ptr, g_gxemb);
    {   // gx_emb = embbf @ Wihembbf^T + bih   (M=2048, N=3072)
        __nv_bfloat16 *Abf, *Bbf;
        cudaGetSymbolAddress((void**)&Abf, g_embbf);
        cudaGetSymbolAddress((void**)&Bbf, g_Wihembbf);
        bf16_mma_kernel<<<dim3(3 * Hh / 64, (Tt * Bb) / 128), 256>>>(
            Abf, Bbf, bih, gxemb_ptr, 3 * Hh, 0);
    }
    gemm_tn_kernel<<<dim3(Hh / 64, (Bb * Ss) / 64), 256>>>(enc, Wk, Hh);
    init_h_kernel<<<(Bb * Hh + 255) / 256, 256>>>(h0);

    // Phase 2: sequential decode
    for (int t = 0; t < Tt; t++) {
        hgemm_kernel<<<256, 256, 65536>>>(Wq, Whh, bhh, t);
        scores_kernel<<<Bb * Ss, 128>>>(vat);
        ctx_kernel<<<dim3(Bb, 8), 128>>>(enc, out_attw, t);
        gru2_kernel<<<256, 192, 65536>>>(Wih, t);
    }

    copy_hT_kernel<<<(Bb * Hh + 255) / 256, 256>>>(out_hT);

    // Phase 3: logits on tensor cores + log_softmax
    {
        __nv_bfloat16 *Abf, *Bbf;
        cudaGetSymbolAddress((void**)&Abf, g_Hbf);
        cudaGetSymbolAddress((void**)&Bbf, g_Woutbf);
        bf16_mma_kernel<<<dim3(Vv / 64, (Tt * Bb) / 128), 256>>>(
            Abf, Bbf, bout, out, Vv, 1);
    }
    logsoftmax_kernel<<<Bb * Tt, 256>>>(out);
}